// round 16
// baseline (speedup 1.0000x reference)
#include <cuda_runtime.h>
#include <float.h>

#define NN 50000
#define NE 800000
#define NG 128
#define GB 1563                                // ceil(NN/32) gemm tiles
#define SCAT_NB 3125                           // NE / 256 exactly

typedef unsigned long long ull;

// ---------------- scratch (device globals; no allocation allowed) -----------
// Replay invariants: g_deg re-zeroed by k_attn(1) epilogue; g_pool re-zeroed
// by k_finalize; everything else fully overwritten each launch.
__device__ float g_q[NN * 128];
__device__ float g_k[NN * 128];
__device__ float g_v[NN * 128];
__device__ float g_h1[NN * 128];
__device__ float g_h2[NN * 128];
__device__ int   g_src[NE];
__device__ int   g_dst[NE];
__device__ int   g_csrc[NE];          // CSR: src node per slot, grouped by dst
__device__ int   g_deg[NN];
__device__ int   g_off[NN];
__device__ int   g_pos[NN];
__device__ int   g_batch[NN];
__device__ float g_pool[2 * NG];
__device__ float g_wf[129];           // fused final weights [128] + bias

// ---------------- packed f32x2 helpers ---------------------------------------
__device__ __forceinline__ ull pack2(float lo, float hi) {
    ull r;
    asm("mov.b64 %0, {%1, %2};" : "=l"(r) : "f"(lo), "f"(hi));
    return r;
}
__device__ __forceinline__ void unpack2(ull v, float& lo, float& hi) {
    asm("mov.b64 {%0, %1}, %2;" : "=f"(lo), "=f"(hi) : "l"(v));
}
__device__ __forceinline__ ull ffma2(ull a, ull b, ull c) {
    ull d;
    asm("fma.rn.f32x2 %0, %1, %2, %3;" : "=l"(d) : "l"(a), "l"(b), "l"(c));
    return d;
}

// ---------------- dtype detect (per-block) + convert + dst histogram --------
__global__ void k_convert(const void* ei, const void* batch) {
    __shared__ int sh_is64;
    if (threadIdx.x == 0) {
        // int64 indices in [0,50000): every high 32-bit word is 0.
        const int* p = (const int*)ei;
        int ok = 1;
#pragma unroll
        for (int j = 0; j < 64; j++)
            if (p[2 * j + 1] != 0) ok = 0;
        sh_is64 = ok;
    }
    __syncthreads();
    int is64 = sh_is64;
    int i = blockIdx.x * blockDim.x + threadIdx.x;
    if (i < NE) {
        int s, d;
        if (is64) {
            const long long* p = (const long long*)ei;
            s = (int)p[i]; d = (int)p[NE + i];
        } else {
            const int* p = (const int*)ei;
            s = p[i]; d = p[NE + i];
        }
        g_src[i] = s; g_dst[i] = d;
        atomicAdd(&g_deg[d], 1);
    }
    if (i < NN) {
        if (is64) g_batch[i] = (int)((const long long*)batch)[i];
        else      g_batch[i] = ((const int*)batch)[i];
    }
}

// ---------------- single-block exclusive scan: g_deg -> g_off/g_pos ---------
__global__ void __launch_bounds__(1024)
k_scan1() {
    __shared__ int ts[1024];
    int t = threadIdx.x;
    const int CH = (NN + 1023) / 1024;             // 49
    int base = t * CH;
    int sum = 0;
    for (int j = 0; j < CH; j++) {
        int i = base + j;
        if (i < NN) sum += g_deg[i];
    }
    ts[t] = sum;
    __syncthreads();
    for (int o = 1; o < 1024; o <<= 1) {
        int u = (t >= o) ? ts[t - o] : 0;
        __syncthreads();
        ts[t] += u;
        __syncthreads();
    }
    int run = t ? ts[t - 1] : 0;                   // exclusive prefix
    for (int j = 0; j < CH; j++) {
        int i = base + j;
        if (i < NN) {
            g_off[i] = run;
            g_pos[i] = run;
            run += g_deg[i];
        }
    }
}

// ---------------- GEMM body (r5 structure, measured best) --------------------
// Selects the true input INSIDE (layer 1 reads g_h1 + relu).
__device__ __forceinline__ void gemm_tile(
    const float* __restrict__ xin, int layer, int tile, int tid,
    const float* __restrict__ wq, const float* __restrict__ bq,
    const float* __restrict__ wk, const float* __restrict__ bk,
    const float* __restrict__ wv, const float* __restrict__ bv,
    const float* __restrict__ ws, const float* __restrict__ bs,
    float (*xs)[32]) {

    const float* src = layer ? g_h1 : xin;

    for (int i = tid; i < 32 * 32; i += 256) {
        int r = i & 31, dg = i >> 5;
        float4 v = make_float4(0.f, 0.f, 0.f, 0.f);
        int node = tile + r;
        if (node < NN) v = *(const float4*)&src[(size_t)node * 128 + dg * 4];
        if (layer) {
            v.x = fmaxf(v.x, 0.f); v.y = fmaxf(v.y, 0.f);
            v.z = fmaxf(v.z, 0.f); v.w = fmaxf(v.w, 0.f);
        }
        xs[dg * 4 + 0][r] = v.x;
        xs[dg * 4 + 1][r] = v.y;
        xs[dg * 4 + 2][r] = v.z;
        xs[dg * 4 + 3][r] = v.w;
    }
    __syncthreads();

    int mat = tid >> 6;
    int rh = (tid >> 5) & 1;
    int c = (tid & 31) * 4;
    int r0 = rh * 16;
    const float* W; const float* B; float* O;
    if (mat == 0)      { W = wq; B = bq; O = g_q; }
    else if (mat == 1) { W = wk; B = bk; O = g_k; }
    else if (mat == 2) { W = wv; B = bv; O = g_v; }
    else               { W = ws; B = bs; O = layer ? g_h2 : g_h1; }

    ull acc0[8], acc1[8], acc2[8], acc3[8];
    {
        float4 b4 = *(const float4*)&B[c];
        ull i0 = pack2(b4.x, b4.x), i1 = pack2(b4.y, b4.y);
        ull i2 = pack2(b4.z, b4.z), i3 = pack2(b4.w, b4.w);
#pragma unroll
        for (int k = 0; k < 8; k++) { acc0[k] = i0; acc1[k] = i1; acc2[k] = i2; acc3[k] = i3; }
    }

#pragma unroll 4
    for (int d = 0; d < 128; d++) {
        float4 w4 = *(const float4*)&W[d * 128 + c];
        ull wa = pack2(w4.x, w4.x);
        ull wb = pack2(w4.y, w4.y);
        ull wc = pack2(w4.z, w4.z);
        ull wd = pack2(w4.w, w4.w);
        ulonglong2 x0 = *(const ulonglong2*)&xs[d][r0];
        ulonglong2 x1 = *(const ulonglong2*)&xs[d][r0 + 4];
        ulonglong2 x2 = *(const ulonglong2*)&xs[d][r0 + 8];
        ulonglong2 x3 = *(const ulonglong2*)&xs[d][r0 + 12];
        acc0[0] = ffma2(x0.x, wa, acc0[0]); acc0[1] = ffma2(x0.y, wa, acc0[1]);
        acc0[2] = ffma2(x1.x, wa, acc0[2]); acc0[3] = ffma2(x1.y, wa, acc0[3]);
        acc0[4] = ffma2(x2.x, wa, acc0[4]); acc0[5] = ffma2(x2.y, wa, acc0[5]);
        acc0[6] = ffma2(x3.x, wa, acc0[6]); acc0[7] = ffma2(x3.y, wa, acc0[7]);
        acc1[0] = ffma2(x0.x, wb, acc1[0]); acc1[1] = ffma2(x0.y, wb, acc1[1]);
        acc1[2] = ffma2(x1.x, wb, acc1[2]); acc1[3] = ffma2(x1.y, wb, acc1[3]);
        acc1[4] = ffma2(x2.x, wb, acc1[4]); acc1[5] = ffma2(x2.y, wb, acc1[5]);
        acc1[6] = ffma2(x3.x, wb, acc1[6]); acc1[7] = ffma2(x3.y, wb, acc1[7]);
        acc2[0] = ffma2(x0.x, wc, acc2[0]); acc2[1] = ffma2(x0.y, wc, acc2[1]);
        acc2[2] = ffma2(x1.x, wc, acc2[2]); acc2[3] = ffma2(x1.y, wc, acc2[3]);
        acc2[4] = ffma2(x2.x, wc, acc2[4]); acc2[5] = ffma2(x2.y, wc, acc2[5]);
        acc2[6] = ffma2(x3.x, wc, acc2[6]); acc2[7] = ffma2(x3.y, wc, acc2[7]);
        acc3[0] = ffma2(x0.x, wd, acc3[0]); acc3[1] = ffma2(x0.y, wd, acc3[1]);
        acc3[2] = ffma2(x1.x, wd, acc3[2]); acc3[3] = ffma2(x1.y, wd, acc3[3]);
        acc3[4] = ffma2(x2.x, wd, acc3[4]); acc3[5] = ffma2(x2.y, wd, acc3[5]);
        acc3[6] = ffma2(x3.x, wd, acc3[6]); acc3[7] = ffma2(x3.y, wd, acc3[7]);
    }

    int lim = min(32, NN - tile);
#pragma unroll
    for (int k = 0; k < 8; k++) {
        float a0l, a0h, a1l, a1h, a2l, a2h, a3l, a3h;
        unpack2(acc0[k], a0l, a0h); unpack2(acc1[k], a1l, a1h);
        unpack2(acc2[k], a2l, a2h); unpack2(acc3[k], a3l, a3h);
        int rr0 = r0 + 2 * k, rr1 = rr0 + 1;
        if (rr0 < lim)
            *(float4*)&O[(size_t)(tile + rr0) * 128 + c] = make_float4(a0l, a1l, a2l, a3l);
        if (rr1 < lim)
            *(float4*)&O[(size_t)(tile + rr1) * 128 + c] = make_float4(a0h, a1h, a2h, a3h);
    }
}

// ---------------- fused: gemm0 | CSR scatter | final-weight fuse ------------
__global__ void __launch_bounds__(256, 2)
k_fused0(const float* __restrict__ xin,
         const float* __restrict__ wq, const float* __restrict__ bq,
         const float* __restrict__ wk, const float* __restrict__ bk,
         const float* __restrict__ wv, const float* __restrict__ bv,
         const float* __restrict__ ws, const float* __restrict__ bs,
         const float* __restrict__ wl, const float* __restrict__ bl,
         const float* __restrict__ wl2, const float* __restrict__ bl2) {
    __shared__ float xs[128][32];
    if (blockIdx.x < GB) {
        gemm_tile(xin, 0, blockIdx.x * 32, threadIdx.x,
                  wq, bq, wk, bk, wv, bv, ws, bs, xs);
    } else if (blockIdx.x < GB + SCAT_NB) {
        int i = (blockIdx.x - GB) * 256 + threadIdx.x;
        if (i < NE) {
            int d = g_dst[i];
            int p = atomicAdd(&g_pos[d], 1);
            g_csrc[p] = g_src[i];
        }
    } else {
        // fusew (128 active threads)
        __shared__ float red[128];
        int d = threadIdx.x;
        if (d < 128) {
            float s = 0.f;
#pragma unroll 4
            for (int c = 0; c < 128; c++) s += wl[d * 128 + c] * wl2[c];
            g_wf[d] = s;
            red[d] = bl[d] * wl2[d];
        }
        __syncthreads();
        for (int o = 64; o; o >>= 1) {
            if (d < o) red[d] += red[d + o];
            __syncthreads();
        }
        if (d == 0) g_wf[128] = red[0] + bl2[0];
    }
}

// ---------------- standalone gemm (layer 1) ----------------------------------
__global__ void __launch_bounds__(256, 2)
k_gemm(const float* __restrict__ xin, int layer,
       const float* __restrict__ wq, const float* __restrict__ bq,
       const float* __restrict__ wk, const float* __restrict__ bk,
       const float* __restrict__ wv, const float* __restrict__ bv,
       const float* __restrict__ ws, const float* __restrict__ bs) {
    __shared__ float xs[128][32];
    gemm_tile(xin, layer, blockIdx.x * 32, threadIdx.x,
              wq, bq, wk, bk, wv, bv, ws, bs, xs);
}

// ---------------- fused attention: warp per destination node -----------------
// r5 mainloop exactly; layer-1 epilogue fuses pooling + g_deg reset.
__global__ void __launch_bounds__(256)
k_attn(int layer) {
    __shared__ float4 qs[8][32];                   // swizzled q rows per warp
    int tid = threadIdx.x, wp = tid >> 5, lane = tid & 31;
    int n = blockIdx.x * 8 + wp;
    if (n >= NN) return;

    float* O = layer ? g_h2 : g_h1;
    const float4* q4 = (const float4*)(g_q + (size_t)n * 128);
    qs[wp][lane ^ (lane >> 3)] = q4[lane];         // bank-conflict swizzle
    __syncwarp();

    int start = g_off[n], deg = g_deg[n];
    int h = lane & 3, el = lane >> 2;
    int hd = lane >> 3;                            // head of owned dims
    float m_own = -FLT_MAX, s_own = 0.f;
    float4 acc = make_float4(0.f, 0.f, 0.f, 0.f);
    const float sc_f = 0.17677669529663687f;       // 1/sqrt(32)

    for (int cch = 0; cch < deg; cch += 8) {
        int ecnt = min(8, deg - cch);
        int sidx = 0;
        if (el < ecnt) sidx = g_csrc[start + cch + el];

        const float4* k4 = (const float4*)(g_k + (size_t)sidx * 128) + h * 8;
        float d0 = 0.f;
#pragma unroll
        for (int j = 0; j < 8; j++) {
            float4 kv = k4[j];
            float4 qv = qs[wp][(h * 8 + j) ^ h];
            d0 += kv.x * qv.x + kv.y * qv.y + kv.z * qv.z + kv.w * qv.w;
        }
        float sc = (el < ecnt) ? d0 * sc_f : -FLT_MAX;

        float cmax = sc;
        cmax = fmaxf(cmax, __shfl_xor_sync(0xffffffffu, cmax, 4));
        cmax = fmaxf(cmax, __shfl_xor_sync(0xffffffffu, cmax, 8));
        cmax = fmaxf(cmax, __shfl_xor_sync(0xffffffffu, cmax, 16));

        float nm = fmaxf(m_own, cmax);
        float scal = __expf(m_own - nm);
        m_own = nm;

        float a = (el < ecnt) ? __expf(sc - m_own) : 0.f;
        float asum = a;
        asum += __shfl_xor_sync(0xffffffffu, asum, 4);
        asum += __shfl_xor_sync(0xffffffffu, asum, 8);
        asum += __shfl_xor_sync(0xffffffffu, asum, 16);
        s_own = s_own * scal + asum;

        // rescale accumulator by own-head factor (factors live in lanes 0..3)
        float rs = __shfl_sync(0xffffffffu, scal, hd);
        acc.x *= rs; acc.y *= rs; acc.z *= rs; acc.w *= rs;

        // accumulate a * v[src]: 1 LDG.128 + 2 shfl per edge
        for (int e2 = 0; e2 < ecnt; e2++) {
            int s2 = __shfl_sync(0xffffffffu, sidx, e2 * 4);
            float ah = __shfl_sync(0xffffffffu, a, e2 * 4 + hd);
            float4 vv = *(const float4*)&g_v[(size_t)s2 * 128 + 4 * lane];
            acc.x = fmaf(ah, vv.x, acc.x);
            acc.y = fmaf(ah, vv.y, acc.y);
            acc.z = fmaf(ah, vv.z, acc.z);
            acc.w = fmaf(ah, vv.w, acc.w);
        }
    }

    float sH = __shfl_sync(0xffffffffu, s_own, hd);
    float inv = (sH > 0.f) ? 1.f / sH : 0.f;
    float4* op = (float4*)&O[(size_t)n * 128 + 4 * lane];
    float4 o = *op;                                // skip term (from gemm)
    o.x = fmaf(acc.x, inv, o.x);
    o.y = fmaf(acc.y, inv, o.y);
    o.z = fmaf(acc.z, inv, o.z);
    o.w = fmaf(acc.w, inv, o.w);
    if (layer == 0) {
        *op = o;                                   // h1 feeds layer-1 gemm
    } else {
        // fused pooling: y = relu(h2 row) . wf
        const float4 wv = *(const float4*)&g_wf[4 * lane];
        float s = fmaxf(o.x, 0.f) * wv.x + fmaxf(o.y, 0.f) * wv.y
                + fmaxf(o.z, 0.f) * wv.z + fmaxf(o.w, 0.f) * wv.w;
#pragma unroll
        for (int of = 16; of; of >>= 1) s += __shfl_xor_sync(0xffffffffu, s, of);
        if (lane == 0) {
            int g = g_batch[n];
            atomicAdd(&g_pool[g], s + g_wf[128]);
            atomicAdd(&g_pool[NG + g], 1.f);
            g_deg[n] = 0;                          // restore replay invariant
        }
    }
}

__global__ void k_finalize(float* out) {
    int g = threadIdx.x;
    out[g] = g_pool[g] / fmaxf(g_pool[NG + g], 1.f);
    g_pool[g] = 0.f;                               // restore replay invariant
    g_pool[NG + g] = 0.f;
}

// ---------------- launch -----------------------------------------------------
extern "C" void kernel_launch(void* const* d_in, const int* in_sizes, int n_in,
                              void* d_out, int out_size) {
    const float* x = (const float*)d_in[0];
    const void* ei = d_in[1];
    const void* batch = d_in[2];
    const float* w[20];
    for (int i = 0; i < 20; i++) w[i] = (const float*)d_in[3 + i];
    float* out = (float*)d_out;

    k_convert<<<(NE + 255) / 256, 256>>>(ei, batch);                   // 0
    k_scan1<<<1, 1024>>>();                                            // 1
    k_fused0<<<GB + SCAT_NB + 1, 256>>>(x, w[0], w[1], w[2], w[3],
                                        w[4], w[5], w[6], w[7],
                                        w[16], w[17], w[18], w[19]);   // 2
    k_attn<<<(NN + 7) / 8, 256>>>(0);                                  // 3 (PROFILED)
    k_gemm<<<(NN + 31) / 32, 256>>>(x, 1, w[8], w[9], w[10], w[11],
                                    w[12], w[13], w[14], w[15]);       // 4
    k_attn<<<(NN + 7) / 8, 256>>>(1);                                  // 5 (pool+reset)
    k_finalize<<<1, NG>>>(out);                                        // 6
}

// round 17
// speedup vs baseline: 1.2759x; 1.2759x over previous
#include <cuda_runtime.h>
#include <float.h>

#define NN 50000
#define NE 800000
#define NG 128
#define SCAN_B 256
#define SCAN_NB ((NN + SCAN_B - 1) / SCAN_B)   // 196
#define GB 1563                                // ceil(NN/32) gemm tiles
#define SCAT_NB 3125                           // NE / 256 exactly

typedef unsigned long long ull;

// ---------------- scratch (device globals; no allocation allowed) -----------
// Replay invariants: g_deg re-zeroed by k_attn(1) epilogue; g_pool re-zeroed
// by k_finalize; everything else fully overwritten each launch.
__device__ float g_q[NN * 128];
__device__ float g_k[NN * 128];       // PERMUTED layout: f4 slot = j*4 + head
__device__ float g_v[NN * 128];
__device__ float g_h1[NN * 128];
__device__ float g_h2[NN * 128];
__device__ int   g_src[NE];
__device__ int   g_dst[NE];
__device__ int   g_csrc[NE];          // CSR: src node per slot, grouped by dst
__device__ int   g_deg[NN];
__device__ int   g_off[NN];
__device__ int   g_pos[NN];
__device__ int   g_tmp[NN];
__device__ int   g_bsum[SCAN_NB];
__device__ int   g_bpre[SCAN_NB];
__device__ int   g_batch[NN];
__device__ float g_pool[2 * NG];
__device__ float g_wf[129];           // fused final weights [128] + bias

// ---------------- packed f32x2 helpers ---------------------------------------
__device__ __forceinline__ ull pack2(float lo, float hi) {
    ull r;
    asm("mov.b64 %0, {%1, %2};" : "=l"(r) : "f"(lo), "f"(hi));
    return r;
}
__device__ __forceinline__ void unpack2(ull v, float& lo, float& hi) {
    asm("mov.b64 {%0, %1}, %2;" : "=f"(lo), "=f"(hi) : "l"(v));
}
__device__ __forceinline__ ull ffma2(ull a, ull b, ull c) {
    ull d;
    asm("fma.rn.f32x2 %0, %1, %2, %3;" : "=l"(d) : "l"(a), "l"(b), "l"(c));
    return d;
}

// ---------------- dtype detect (per-block) + convert + dst histogram --------
__global__ void k_convert(const void* ei, const void* batch) {
    __shared__ int sh_is64;
    if (threadIdx.x == 0) {
        // int64 indices in [0,50000): every high 32-bit word is 0.
        const int* p = (const int*)ei;
        int ok = 1;
#pragma unroll
        for (int j = 0; j < 64; j++)
            if (p[2 * j + 1] != 0) ok = 0;
        sh_is64 = ok;
    }
    __syncthreads();
    int is64 = sh_is64;
    int i = blockIdx.x * blockDim.x + threadIdx.x;
    if (i < NE) {
        int s, d;
        if (is64) {
            const long long* p = (const long long*)ei;
            s = (int)p[i]; d = (int)p[NE + i];
        } else {
            const int* p = (const int*)ei;
            s = p[i]; d = p[NE + i];
        }
        g_src[i] = s; g_dst[i] = d;
        atomicAdd(&g_deg[d], 1);
    }
    if (i < NN) {
        if (is64) g_batch[i] = (int)((const long long*)batch)[i];
        else      g_batch[i] = ((const int*)batch)[i];
    }
}

// ---------------- 3-kernel exclusive scan of g_deg -> g_off -----------------
__global__ void k_scan_a() {
    __shared__ int sh[SCAN_B];
    int t = threadIdx.x, i = blockIdx.x * SCAN_B + t;
    int v = (i < NN) ? g_deg[i] : 0;
    sh[t] = v;
    __syncthreads();
    for (int o = 1; o < SCAN_B; o <<= 1) {
        int u = (t >= o) ? sh[t - o] : 0;
        __syncthreads();
        sh[t] += u;
        __syncthreads();
    }
    if (i < NN) g_tmp[i] = sh[t];                  // inclusive scan (local)
    if (t == SCAN_B - 1) g_bsum[blockIdx.x] = sh[t];
}

__global__ void k_scan_b() {
    __shared__ int sh[SCAN_B];
    int t = threadIdx.x;
    int v = (t < SCAN_NB) ? g_bsum[t] : 0;
    sh[t] = v;
    __syncthreads();
    for (int o = 1; o < SCAN_B; o <<= 1) {
        int u = (t >= o) ? sh[t - o] : 0;
        __syncthreads();
        sh[t] += u;
        __syncthreads();
    }
    if (t < SCAN_NB) g_bpre[t] = sh[t] - v;        // exclusive block prefix
}

__global__ void k_scan_c() {
    int t = threadIdx.x, i = blockIdx.x * SCAN_B + t;
    if (i < NN) {
        int off = g_tmp[i] - g_deg[i] + g_bpre[blockIdx.x];
        g_off[i] = off;
        g_pos[i] = off;
    }
}

// ---------------- GEMM body (r5 structure, measured best) --------------------
// Selects the true input INSIDE (layer 1 reads g_h1 + relu). For mat==1 (k)
// the store column is permuted (f4 slot h*8+j -> j*4+h) so the attention
// k-gather becomes quad-contiguous (sector-efficient). Same 512B row region,
// still coalesced; values bit-identical.
__device__ __forceinline__ void gemm_tile(
    const float* __restrict__ xin, int layer, int tile, int tid,
    const float* __restrict__ wq, const float* __restrict__ bq,
    const float* __restrict__ wk, const float* __restrict__ bk,
    const float* __restrict__ wv, const float* __restrict__ bv,
    const float* __restrict__ ws, const float* __restrict__ bs,
    float (*xs)[32]) {

    const float* src = layer ? g_h1 : xin;

    for (int i = tid; i < 32 * 32; i += 256) {
        int r = i & 31, dg = i >> 5;
        float4 v = make_float4(0.f, 0.f, 0.f, 0.f);
        int node = tile + r;
        if (node < NN) v = *(const float4*)&src[(size_t)node * 128 + dg * 4];
        if (layer) {
            v.x = fmaxf(v.x, 0.f); v.y = fmaxf(v.y, 0.f);
            v.z = fmaxf(v.z, 0.f); v.w = fmaxf(v.w, 0.f);
        }
        xs[dg * 4 + 0][r] = v.x;
        xs[dg * 4 + 1][r] = v.y;
        xs[dg * 4 + 2][r] = v.z;
        xs[dg * 4 + 3][r] = v.w;
    }
    __syncthreads();

    int mat = tid >> 6;
    int rh = (tid >> 5) & 1;
    int c = (tid & 31) * 4;
    int r0 = rh * 16;
    const float* W; const float* B; float* O;
    if (mat == 0)      { W = wq; B = bq; O = g_q; }
    else if (mat == 1) { W = wk; B = bk; O = g_k; }
    else if (mat == 2) { W = wv; B = bv; O = g_v; }
    else               { W = ws; B = bs; O = layer ? g_h2 : g_h1; }

    ull acc0[8], acc1[8], acc2[8], acc3[8];
    {
        float4 b4 = *(const float4*)&B[c];
        ull i0 = pack2(b4.x, b4.x), i1 = pack2(b4.y, b4.y);
        ull i2 = pack2(b4.z, b4.z), i3 = pack2(b4.w, b4.w);
#pragma unroll
        for (int k = 0; k < 8; k++) { acc0[k] = i0; acc1[k] = i1; acc2[k] = i2; acc3[k] = i3; }
    }

#pragma unroll 4
    for (int d = 0; d < 128; d++) {
        float4 w4 = *(const float4*)&W[d * 128 + c];
        ull wa = pack2(w4.x, w4.x);
        ull wb = pack2(w4.y, w4.y);
        ull wc = pack2(w4.z, w4.z);
        ull wd = pack2(w4.w, w4.w);
        ulonglong2 x0 = *(const ulonglong2*)&xs[d][r0];
        ulonglong2 x1 = *(const ulonglong2*)&xs[d][r0 + 4];
        ulonglong2 x2 = *(const ulonglong2*)&xs[d][r0 + 8];
        ulonglong2 x3 = *(const ulonglong2*)&xs[d][r0 + 12];
        acc0[0] = ffma2(x0.x, wa, acc0[0]); acc0[1] = ffma2(x0.y, wa, acc0[1]);
        acc0[2] = ffma2(x1.x, wa, acc0[2]); acc0[3] = ffma2(x1.y, wa, acc0[3]);
        acc0[4] = ffma2(x2.x, wa, acc0[4]); acc0[5] = ffma2(x2.y, wa, acc0[5]);
        acc0[6] = ffma2(x3.x, wa, acc0[6]); acc0[7] = ffma2(x3.y, wa, acc0[7]);
        acc1[0] = ffma2(x0.x, wb, acc1[0]); acc1[1] = ffma2(x0.y, wb, acc1[1]);
        acc1[2] = ffma2(x1.x, wb, acc1[2]); acc1[3] = ffma2(x1.y, wb, acc1[3]);
        acc1[4] = ffma2(x2.x, wb, acc1[4]); acc1[5] = ffma2(x2.y, wb, acc1[5]);
        acc1[6] = ffma2(x3.x, wb, acc1[6]); acc1[7] = ffma2(x3.y, wb, acc1[7]);
        acc2[0] = ffma2(x0.x, wc, acc2[0]); acc2[1] = ffma2(x0.y, wc, acc2[1]);
        acc2[2] = ffma2(x1.x, wc, acc2[2]); acc2[3] = ffma2(x1.y, wc, acc2[3]);
        acc2[4] = ffma2(x2.x, wc, acc2[4]); acc2[5] = ffma2(x2.y, wc, acc2[5]);
        acc2[6] = ffma2(x3.x, wc, acc2[6]); acc2[7] = ffma2(x3.y, wc, acc2[7]);
        acc3[0] = ffma2(x0.x, wd, acc3[0]); acc3[1] = ffma2(x0.y, wd, acc3[1]);
        acc3[2] = ffma2(x1.x, wd, acc3[2]); acc3[3] = ffma2(x1.y, wd, acc3[3]);
        acc3[4] = ffma2(x2.x, wd, acc3[4]); acc3[5] = ffma2(x2.y, wd, acc3[5]);
        acc3[6] = ffma2(x3.x, wd, acc3[6]); acc3[7] = ffma2(x3.y, wd, acc3[7]);
    }

    // k layout permutation: logical f4 slot (c>>2) = h*8+j -> physical j*4+h
    int cs = c;
    if (mat == 1) {
        int f4 = c >> 2;
        cs = (((f4 & 7) << 2) | (f4 >> 3)) << 2;
    }

    int lim = min(32, NN - tile);
#pragma unroll
    for (int k = 0; k < 8; k++) {
        float a0l, a0h, a1l, a1h, a2l, a2h, a3l, a3h;
        unpack2(acc0[k], a0l, a0h); unpack2(acc1[k], a1l, a1h);
        unpack2(acc2[k], a2l, a2h); unpack2(acc3[k], a3l, a3h);
        int rr0 = r0 + 2 * k, rr1 = rr0 + 1;
        if (rr0 < lim)
            *(float4*)&O[(size_t)(tile + rr0) * 128 + cs] = make_float4(a0l, a1l, a2l, a3l);
        if (rr1 < lim)
            *(float4*)&O[(size_t)(tile + rr1) * 128 + cs] = make_float4(a0h, a1h, a2h, a3h);
    }
}

// ---------------- fused: gemm0 | CSR scatter | final-weight fuse ------------
__global__ void __launch_bounds__(256, 2)
k_fused0(const float* __restrict__ xin,
         const float* __restrict__ wq, const float* __restrict__ bq,
         const float* __restrict__ wk, const float* __restrict__ bk,
         const float* __restrict__ wv, const float* __restrict__ bv,
         const float* __restrict__ ws, const float* __restrict__ bs,
         const float* __restrict__ wl, const float* __restrict__ bl,
         const float* __restrict__ wl2, const float* __restrict__ bl2) {
    __shared__ float xs[128][32];
    if (blockIdx.x < GB) {
        gemm_tile(xin, 0, blockIdx.x * 32, threadIdx.x,
                  wq, bq, wk, bk, wv, bv, ws, bs, xs);
    } else if (blockIdx.x < GB + SCAT_NB) {
        int i = (blockIdx.x - GB) * 256 + threadIdx.x;
        if (i < NE) {
            int d = g_dst[i];
            int p = atomicAdd(&g_pos[d], 1);
            g_csrc[p] = g_src[i];
        }
    } else {
        // fusew (128 active threads)
        __shared__ float red[128];
        int d = threadIdx.x;
        if (d < 128) {
            float s = 0.f;
#pragma unroll 4
            for (int c = 0; c < 128; c++) s += wl[d * 128 + c] * wl2[c];
            g_wf[d] = s;
            red[d] = bl[d] * wl2[d];
        }
        __syncthreads();
        for (int o = 64; o; o >>= 1) {
            if (d < o) red[d] += red[d + o];
            __syncthreads();
        }
        if (d == 0) g_wf[128] = red[0] + bl2[0];
    }
}

// ---------------- standalone gemm (layer 1) ----------------------------------
__global__ void __launch_bounds__(256, 2)
k_gemm(const float* __restrict__ xin, int layer,
       const float* __restrict__ wq, const float* __restrict__ bq,
       const float* __restrict__ wk, const float* __restrict__ bk,
       const float* __restrict__ wv, const float* __restrict__ bv,
       const float* __restrict__ ws, const float* __restrict__ bs) {
    __shared__ float xs[128][32];
    gemm_tile(xin, layer, blockIdx.x * 32, threadIdx.x,
              wq, bq, wk, bk, wv, bv, ws, bs, xs);
}

// ---------------- fused attention: warp per destination node -----------------
// r5 mainloop; k read uses the permuted layout (f4 slot j*4+h) so each score
// LDG is quad-contiguous (8 lines/instr instead of 32). Math bit-identical.
// Layer-1 epilogue fuses pooling + g_deg reset.
__global__ void __launch_bounds__(256)
k_attn(int layer) {
    __shared__ float4 qs[8][32];                   // swizzled q rows per warp
    int tid = threadIdx.x, wp = tid >> 5, lane = tid & 31;
    int n = blockIdx.x * 8 + wp;
    if (n >= NN) return;

    float* O = layer ? g_h2 : g_h1;
    const float4* q4 = (const float4*)(g_q + (size_t)n * 128);
    qs[wp][lane ^ (lane >> 3)] = q4[lane];         // bank-conflict swizzle
    __syncwarp();

    int start = g_off[n], deg = g_deg[n];
    int h = lane & 3, el = lane >> 2;
    int hd = lane >> 3;                            // head of owned dims
    float m_own = -FLT_MAX, s_own = 0.f;
    float4 acc = make_float4(0.f, 0.f, 0.f, 0.f);
    const float sc_f = 0.17677669529663687f;       // 1/sqrt(32)

    for (int cch = 0; cch < deg; cch += 8) {
        int ecnt = min(8, deg - cch);
        int sidx = 0;
        if (el < ecnt) sidx = g_csrc[start + cch + el];

        const float4* k4 = (const float4*)(g_k + (size_t)sidx * 128);
        float d0 = 0.f;
#pragma unroll
        for (int j = 0; j < 8; j++) {
            float4 kv = k4[j * 4 + h];             // permuted: quad-contiguous
            float4 qv = qs[wp][(h * 8 + j) ^ h];
            d0 += kv.x * qv.x + kv.y * qv.y + kv.z * qv.z + kv.w * qv.w;
        }
        float sc = (el < ecnt) ? d0 * sc_f : -FLT_MAX;

        float cmax = sc;
        cmax = fmaxf(cmax, __shfl_xor_sync(0xffffffffu, cmax, 4));
        cmax = fmaxf(cmax, __shfl_xor_sync(0xffffffffu, cmax, 8));
        cmax = fmaxf(cmax, __shfl_xor_sync(0xffffffffu, cmax, 16));

        float nm = fmaxf(m_own, cmax);
        float scal = __expf(m_own - nm);
        m_own = nm;

        float a = (el < ecnt) ? __expf(sc - m_own) : 0.f;
        float asum = a;
        asum += __shfl_xor_sync(0xffffffffu, asum, 4);
        asum += __shfl_xor_sync(0xffffffffu, asum, 8);
        asum += __shfl_xor_sync(0xffffffffu, asum, 16);
        s_own = s_own * scal + asum;

        // rescale accumulator by own-head factor (factors live in lanes 0..3)
        float rs = __shfl_sync(0xffffffffu, scal, hd);
        acc.x *= rs; acc.y *= rs; acc.z *= rs; acc.w *= rs;

        // accumulate a * v[src]: 1 LDG.128 + 2 shfl per edge
        for (int e2 = 0; e2 < ecnt; e2++) {
            int s2 = __shfl_sync(0xffffffffu, sidx, e2 * 4);
            float ah = __shfl_sync(0xffffffffu, a, e2 * 4 + hd);
            float4 vv = *(const float4*)&g_v[(size_t)s2 * 128 + 4 * lane];
            acc.x = fmaf(ah, vv.x, acc.x);
            acc.y = fmaf(ah, vv.y, acc.y);
            acc.z = fmaf(ah, vv.z, acc.z);
            acc.w = fmaf(ah, vv.w, acc.w);
        }
    }

    float sH = __shfl_sync(0xffffffffu, s_own, hd);
    float inv = (sH > 0.f) ? 1.f / sH : 0.f;
    float4* op = (float4*)&O[(size_t)n * 128 + 4 * lane];
    float4 o = *op;                                // skip term (from gemm)
    o.x = fmaf(acc.x, inv, o.x);
    o.y = fmaf(acc.y, inv, o.y);
    o.z = fmaf(acc.z, inv, o.z);
    o.w = fmaf(acc.w, inv, o.w);
    if (layer == 0) {
        *op = o;                                   // h1 feeds layer-1 gemm
    } else {
        // fused pooling: y = relu(h2 row) . wf
        const float4 wv = *(const float4*)&g_wf[4 * lane];
        float s = fmaxf(o.x, 0.f) * wv.x + fmaxf(o.y, 0.f) * wv.y
                + fmaxf(o.z, 0.f) * wv.z + fmaxf(o.w, 0.f) * wv.w;
#pragma unroll
        for (int of = 16; of; of >>= 1) s += __shfl_xor_sync(0xffffffffu, s, of);
        if (lane == 0) {
            int g = g_batch[n];
            atomicAdd(&g_pool[g], s + g_wf[128]);
            atomicAdd(&g_pool[NG + g], 1.f);
            g_deg[n] = 0;                          // restore replay invariant
        }
    }
}

__global__ void k_finalize(float* out) {
    int g = threadIdx.x;
    out[g] = g_pool[g] / fmaxf(g_pool[NG + g], 1.f);
    g_pool[g] = 0.f;                               // restore replay invariant
    g_pool[NG + g] = 0.f;
}

// ---------------- launch -----------------------------------------------------
extern "C" void kernel_launch(void* const* d_in, const int* in_sizes, int n_in,
                              void* d_out, int out_size) {
    const float* x = (const float*)d_in[0];
    const void* ei = d_in[1];
    const void* batch = d_in[2];
    const float* w[20];
    for (int i = 0; i < 20; i++) w[i] = (const float*)d_in[3 + i];
    float* out = (float*)d_out;

    k_convert<<<(NE + 255) / 256, 256>>>(ei, batch);                   // 0
    k_scan_a<<<SCAN_NB, SCAN_B>>>();                                   // 1
    k_scan_b<<<1, SCAN_B>>>();                                         // 2
    k_scan_c<<<SCAN_NB, SCAN_B>>>();                                   // 3
    k_fused0<<<GB + SCAT_NB + 1, 256>>>(x, w[0], w[1], w[2], w[3],
                                        w[4], w[5], w[6], w[7],
                                        w[16], w[17], w[18], w[19]);   // 4
    k_attn<<<(NN + 7) / 8, 256>>>(0);                                  // 5
    k_gemm<<<(NN + 31) / 32, 256>>>(x, 1, w[8], w[9], w[10], w[11],
                                    w[12], w[13], w[14], w[15]);       // 6
    k_attn<<<(NN + 7) / 8, 256>>>(1);                                  // 7 (pool+reset)
    k_finalize<<<1, NG>>>(out);                                        // 8
}